// round 11
// baseline (speedup 1.0000x reference)
#include <cuda_runtime.h>
#include <cuda_fp16.h>

// Problem constants (fixed by the reference).
#define NN 100000
#define DD 64
#define NROW4 16             // float4s per 64-float fp32 row
#define NE 1600000
#define NB 98                // ceil(NN / 1024) scan blocks
#define NE_PAD (NE + 4 * NN) // padded adjacency capacity (gaps never read)
#define READYBIT 0x40000000

// Chebyshev coefficients for lambda_max = 2.0 (constant-fold: C1A=-1, C1B=0,
// C2A=-2, C2B=0).
#define C1A (-2.0f / 2.0f)
#define C1B (2.0f / 2.0f - 1.0f)
#define C2A (-4.0f / 2.0f)
#define C2B (4.0f / 2.0f - 2.0f)

typedef unsigned long long ull;

// Scratch (device globals: no allocation allowed in kernel_launch).
__device__ int    g_degi  [NN];
__device__ int    g_tot   [128];        // per-block padded totals | READYBIT
__device__ int    g_rowptr[NN];         // aligned segment starts (mult. of 4)
__device__ int    g_cursor[NN];
__device__ __align__(16) int g_adj[NE_PAD];
__device__ float  g_norm  [NN];
__device__ float  g_norm2 [NN];
__device__ uint4  g_xs16  [NN * 8];     // fp16 rows: norm[s]*feat[s]
__device__ uint4  g_y16   [NN * 8];     // fp16 rows: norm2[s]*h0[s]
__device__ float4 g_h0    [NN * NROW4]; // fp32 aggregation sums, pass 1
__device__ float4 g_h1    [NN * NROW4]; // fp32 aggregation sums, pass 2 (xC1A)

// ---------------------------------------------------------------------------
// bit-cast helpers (no HW cost)
// ---------------------------------------------------------------------------
__device__ __forceinline__ float2 u32_to_f2(unsigned u) {
    __half2 h = *reinterpret_cast<__half2*>(&u);
    return __half22float2(h);
}
__device__ __forceinline__ unsigned h2_to_u32(__half2 h) {
    return *reinterpret_cast<unsigned*>(&h);
}

// ---------------------------------------------------------------------------
// f32x2 packed-FMA helpers (Blackwell)
// ---------------------------------------------------------------------------
__device__ __forceinline__ ull pack2(float v) {
    ull r;
    asm("mov.b64 %0, {%1, %1};" : "=l"(r) : "f"(v));
    return r;
}
__device__ __forceinline__ void fma2(ull& d, ull a, ull b) {
    asm("fma.rn.f32x2 %0, %1, %2, %0;" : "+l"(d) : "l"(a), "l"(b));
}
__device__ __forceinline__ float2 unpack2(ull v) {
    float2 r;
    asm("mov.b64 {%0, %1}, %2;" : "=f"(r.x), "=f"(r.y) : "l"(v));
    return r;
}

// ---------------------------------------------------------------------------
// 1) degree histogram (int): deg[dst] += 1
// ---------------------------------------------------------------------------
__global__ void deg_kernel(const int4* __restrict__ dst4) {
    int t = blockIdx.x * blockDim.x + threadIdx.x;
    if (t < NE / 4) {
        int4 d = __ldg(dst4 + t);
        atomicAdd(&g_degi[d.x], 1);
        atomicAdd(&g_degi[d.y], 1);
        atomicAdd(&g_degi[d.z], 1);
        atomicAdd(&g_degi[d.w], 1);
    }
}

// ---------------------------------------------------------------------------
// 2) single-kernel scan (decoupled lookback, 98 co-resident blocks):
//    exclusive scan of PADDED degrees -> aligned starts; also norm / norm2.
// ---------------------------------------------------------------------------
__global__ __launch_bounds__(1024) void scan_kernel() {
    __shared__ int wsum[32];
    __shared__ int pre[128];
    __shared__ int s_off;
    int tid = threadIdx.x, lane = tid & 31, wid = tid >> 5;
    int b = blockIdx.x;
    int i = b * 1024 + tid;
    int deg = (i < NN) ? g_degi[i] : 0;
    int v = (deg + 3) & ~3;          // padded degree (aligned segment size)
    int x = v;
#pragma unroll
    for (int off = 1; off < 32; off <<= 1) {
        int y = __shfl_up_sync(~0u, x, off);
        if (lane >= off) x += y;
    }
    if (lane == 31) wsum[wid] = x;
    __syncthreads();
    if (wid == 0) {
        int w = wsum[lane];
#pragma unroll
        for (int off = 1; off < 32; off <<= 1) {
            int y = __shfl_up_sync(~0u, w, off);
            if (lane >= off) w += y;
        }
        wsum[lane] = w;
    }
    __syncthreads();
    int warpoff = (wid > 0) ? wsum[wid - 1] : 0;
    int btotal  = wsum[31];

    if (tid == 0) atomicExch(&g_tot[b], btotal | READYBIT);

    if (tid < b) {
        int p;
        do { p = atomicAdd(&g_tot[tid], 0); } while (!(p & READYBIT));
        pre[tid] = p & ~READYBIT;
    } else if (tid < 128) {
        pre[tid] = 0;
    }
    __syncthreads();
    if (wid == 0) {
        int s = pre[lane] + pre[lane + 32] + pre[lane + 64] + pre[lane + 96];
#pragma unroll
        for (int off = 16; off > 0; off >>= 1)
            s += __shfl_down_sync(~0u, s, off);
        if (lane == 0) s_off = s;
    }
    __syncthreads();

    if (i < NN) {
        int ex = s_off + warpoff + x - v;   // exclusive padded prefix
        g_rowptr[i] = ex;
        g_cursor[i] = ex;
        float nv = rsqrtf(fmaxf((float)deg, 1.0f));
        g_norm[i]  = nv;
        g_norm2[i] = nv * nv;
    }
}

// ---------------------------------------------------------------------------
// 3) CSR fill: adj[cursor[dst]++] = src  (exact lengths; gaps never read)
// ---------------------------------------------------------------------------
__global__ void fill_kernel(const int4* __restrict__ src4,
                            const int4* __restrict__ dst4) {
    int t = blockIdx.x * blockDim.x + threadIdx.x;
    if (t < NE / 4) {
        int4 s = __ldg(src4 + t);
        int4 d = __ldg(dst4 + t);
        g_adj[atomicAdd(&g_cursor[d.x], 1)] = s.x;
        g_adj[atomicAdd(&g_cursor[d.y], 1)] = s.y;
        g_adj[atomicAdd(&g_cursor[d.z], 1)] = s.z;
        g_adj[atomicAdd(&g_cursor[d.w], 1)] = s.w;
    }
}

// ---------------------------------------------------------------------------
// 4) gemm0_xs16: out = feat @ (W0 - W2) + bias   AND   xs16 = half(norm*feat)
//    (t0@W0 + t2@W2 == t0@(W0-W2) + t2'@W2 with t2' = C2A*n*h1 + C2B*t1)
//    Runs on the side stream, overlapped with fill.
// ---------------------------------------------------------------------------
__global__ __launch_bounds__(256) void gemm0_xs16_kernel(
    const float4* __restrict__ feat4,
    const float4* __restrict__ W4,
    const float4* __restrict__ bias4,
    float4* __restrict__ out4) {
    __shared__ __align__(16) float Ws[64 * 64];   // W0 - W2, 16 KB
    {
        float4* Ws4 = reinterpret_cast<float4*>(Ws);
        for (int i = threadIdx.x; i < 1024; i += 256) {
            float4 w0 = __ldg(W4 + i);
            float4 w2 = __ldg(W4 + 2048 + i);
            Ws4[i] = make_float4(w0.x - w2.x, w0.y - w2.y,
                                 w0.z - w2.z, w0.w - w2.w);
        }
    }

    const int base = blockIdx.x * 256;

    // xs16 production for this block's 256 rows (independent of Ws).
#pragma unroll
    for (int k = 0; k < 8; k++) {
        int idx = k * 256 + threadIdx.x;      // 0..2047
        int row = base + (idx >> 3);
        int c   = idx & 7;
        if (row < NN) {
            float nv = g_norm[row];
            float4 f0 = __ldg(feat4 + (row << 4) + c * 2);
            float4 f1 = __ldg(feat4 + (row << 4) + c * 2 + 1);
            uint4 u;
            u.x = h2_to_u32(__floats2half2_rn(nv * f0.x, nv * f0.y));
            u.y = h2_to_u32(__floats2half2_rn(nv * f0.z, nv * f0.w));
            u.z = h2_to_u32(__floats2half2_rn(nv * f1.x, nv * f1.y));
            u.w = h2_to_u32(__floats2half2_rn(nv * f1.z, nv * f1.w));
            g_xs16[row * 8 + c] = u;
        }
    }
    __syncthreads();

    const int cg = threadIdx.x >> 6;
    const int rg = threadIdx.x & 63;

    int   rows[4];
    bool  valid[4];
#pragma unroll
    for (int r = 0; r < 4; r++) {
        int row  = base + rg + 64 * r;
        valid[r] = row < NN;
        rows[r]  = valid[r] ? row : 0;
    }

    ull acc[4][8];
#pragma unroll
    for (int r = 0; r < 4; r++)
#pragma unroll
        for (int cp = 0; cp < 8; cp++) acc[r][cp] = 0ULL;

    const ulonglong2* Wp = reinterpret_cast<const ulonglong2*>(Ws);

    for (int dc = 0; dc < 16; dc++) {
        float4 a0[4];
#pragma unroll
        for (int r = 0; r < 4; r++)
            a0[r] = __ldg(feat4 + (rows[r] << 4) + dc);
#pragma unroll
        for (int s = 0; s < 4; s++) {
            const int d = dc * 4 + s;
            ull tt[4];
#pragma unroll
            for (int r = 0; r < 4; r++)
                tt[r] = pack2(reinterpret_cast<const float*>(&a0[r])[s]);
            const ulonglong2* p = Wp + (d * 16 + cg * 4);
            ull w[8];
#pragma unroll
            for (int j = 0; j < 4; j++) {
                ulonglong2 v = p[j];
                w[2 * j]     = v.x;
                w[2 * j + 1] = v.y;
            }
#pragma unroll
            for (int r = 0; r < 4; r++)
#pragma unroll
                for (int cp = 0; cp < 8; cp++)
                    fma2(acc[r][cp], tt[r], w[cp]);
        }
    }

    float4 b4[4];
#pragma unroll
    for (int j = 0; j < 4; j++) b4[j] = __ldg(bias4 + cg * 4 + j);
#pragma unroll
    for (int r = 0; r < 4; r++) {
        if (!valid[r]) continue;
#pragma unroll
        for (int j = 0; j < 4; j++) {
            float2 lo = unpack2(acc[r][2 * j]);
            float2 hi = unpack2(acc[r][2 * j + 1]);
            float4 o;
            o.x = lo.x + b4[j].x;
            o.y = lo.y + b4[j].y;
            o.z = hi.x + b4[j].z;
            o.w = hi.y + b4[j].w;
            out4[(rows[r] << 4) + cg * 4 + j] = o;
        }
    }
}

// ---------------------------------------------------------------------------
// 5) gather passes. 8 threads per node; each thread owns 8 halves (16B).
//    PASS 0: h0[i] = sum xs16[s]; epilogue writes h0 (fp32) and
//            y16[i] = half(norm2[i]*h0[i]).
//    PASS 1: h1[i] = C1A * sum y16[s]  (fp32).
// ---------------------------------------------------------------------------
template <int PASS>
__global__ __launch_bounds__(256) void gather_kernel() {
    int t = blockIdx.x * blockDim.x + threadIdx.x;
    if (t >= NN * 8) return;
    int i = t >> 3;
    int c = t & 7;

    int j   = g_rowptr[i];       // multiple of 4
    int end = j + g_degi[i];
    const uint4* __restrict__ src = (PASS == 0) ? g_xs16 : g_y16;

    float a0 = 0.f, a1 = 0.f, a2 = 0.f, a3 = 0.f;
    float a4 = 0.f, a5 = 0.f, a6 = 0.f, a7 = 0.f;
    float b0 = 0.f, b1 = 0.f, b2 = 0.f, b3 = 0.f;
    float b4 = 0.f, b5 = 0.f, b6 = 0.f, b7 = 0.f;

#define EDGE_ACC(P0,P1,P2,P3,P4,P5,P6,P7, S)                                 \
    {                                                                        \
        uint4 u = __ldg(src + ((S) << 3) + c);                               \
        float2 f0 = u32_to_f2(u.x);                                          \
        float2 f1 = u32_to_f2(u.y);                                          \
        float2 f2 = u32_to_f2(u.z);                                          \
        float2 f3 = u32_to_f2(u.w);                                          \
        P0 += f0.x; P1 += f0.y; P2 += f1.x; P3 += f1.y;                      \
        P4 += f2.x; P5 += f2.y; P6 += f3.x; P7 += f3.y;                      \
    }
#define EDGE_A(S) EDGE_ACC(a0,a1,a2,a3,a4,a5,a6,a7, S)
#define EDGE_B(S) EDGE_ACC(b0,b1,b2,b3,b4,b5,b6,b7, S)

    for (; j + 8 <= end; j += 8) {
        int4 p0 = *reinterpret_cast<const int4*>(&g_adj[j]);
        int4 p1 = *reinterpret_cast<const int4*>(&g_adj[j + 4]);
        EDGE_A(p0.x); EDGE_B(p0.y); EDGE_A(p0.z); EDGE_B(p0.w);
        EDGE_A(p1.x); EDGE_B(p1.y); EDGE_A(p1.z); EDGE_B(p1.w);
    }
    if (j + 4 <= end) {
        int4 p0 = *reinterpret_cast<const int4*>(&g_adj[j]);
        EDGE_A(p0.x); EDGE_B(p0.y); EDGE_A(p0.z); EDGE_B(p0.w);
        j += 4;
    }
    for (; j < end; j++) {
        EDGE_A(g_adj[j]);
    }
#undef EDGE_A
#undef EDGE_B
#undef EDGE_ACC

    float r0 = a0 + b0, r1 = a1 + b1, r2 = a2 + b2, r3 = a3 + b3;
    float r4 = a4 + b4, r5 = a5 + b5, r6 = a6 + b6, r7 = a7 + b7;

    if (PASS == 0) {
        g_h0[(i << 4) + c * 2]     = make_float4(r0, r1, r2, r3);
        g_h0[(i << 4) + c * 2 + 1] = make_float4(r4, r5, r6, r7);
        float n2 = g_norm2[i];
        uint4 u;
        u.x = h2_to_u32(__floats2half2_rn(n2 * r0, n2 * r1));
        u.y = h2_to_u32(__floats2half2_rn(n2 * r2, n2 * r3));
        u.z = h2_to_u32(__floats2half2_rn(n2 * r4, n2 * r5));
        u.w = h2_to_u32(__floats2half2_rn(n2 * r6, n2 * r7));
        g_y16[t] = u;
    } else {
        g_h1[(i << 4) + c * 2] =
            make_float4(C1A * r0, C1A * r1, C1A * r2, C1A * r3);
        g_h1[(i << 4) + c * 2 + 1] =
            make_float4(C1A * r4, C1A * r5, C1A * r6, C1A * r7);
    }
}

// ---------------------------------------------------------------------------
// 6) final2: out += t1@W1 + t2'@W2
//    t1 = C1A*n*h0;  t2' = C2A*n*h1 + C2B*t1  (the -t0 part was folded into
//    gemm0's W0-W2). Reads only h0/h1; accumulates onto out.
// ---------------------------------------------------------------------------
__global__ __launch_bounds__(256) void final2_kernel(
    const float4* __restrict__ W4,
    float4* __restrict__ out4) {
    __shared__ __align__(16) float Ws[2 * 64 * 64];   // W1, W2: 32 KB
    {
        float4* Ws4 = reinterpret_cast<float4*>(Ws);
        for (int i = threadIdx.x; i < 2048; i += 256)
            Ws4[i] = __ldg(W4 + 1024 + i);
    }
    __syncthreads();

    const int cg   = threadIdx.x >> 6;
    const int rg   = threadIdx.x & 63;
    const int base = blockIdx.x * 256;

    int   rows[4];
    bool  valid[4];
    float n[4];
#pragma unroll
    for (int r = 0; r < 4; r++) {
        int row  = base + rg + 64 * r;
        valid[r] = row < NN;
        rows[r]  = valid[r] ? row : 0;
        n[r]     = g_norm[rows[r]];
    }

    ull acc[4][8];
#pragma unroll
    for (int r = 0; r < 4; r++)
#pragma unroll
        for (int cp = 0; cp < 8; cp++) acc[r][cp] = 0ULL;

    const ulonglong2* Wp = reinterpret_cast<const ulonglong2*>(Ws);

    for (int dc = 0; dc < 16; dc++) {
        float4 a1[4], a2[4];
#pragma unroll
        for (int r = 0; r < 4; r++) {
            int b = (rows[r] << 4) + dc;
            a1[r] = g_h0[b];
            a2[r] = g_h1[b];
        }
#pragma unroll
        for (int s = 0; s < 4; s++) {
            const int d = dc * 4 + s;
            ull tt[2][4];
#pragma unroll
            for (int r = 0; r < 4; r++) {
                float h0v = reinterpret_cast<const float*>(&a1[r])[s];
                float h1v = reinterpret_cast<const float*>(&a2[r])[s];
                float t1 = C1A * n[r] * h0v;
                float t2 = fmaf(C2A * n[r], h1v, C2B * t1);
                tt[0][r] = pack2(t1);
                tt[1][r] = pack2(t2);
            }
#pragma unroll
            for (int k = 0; k < 2; k++) {
                const ulonglong2* p = Wp + (k * 1024 + d * 16 + cg * 4);
                ull w[8];
#pragma unroll
                for (int j = 0; j < 4; j++) {
                    ulonglong2 v = p[j];       // LDS.128, warp-uniform broadcast
                    w[2 * j]     = v.x;
                    w[2 * j + 1] = v.y;
                }
#pragma unroll
                for (int r = 0; r < 4; r++)
#pragma unroll
                    for (int cp = 0; cp < 8; cp++)
                        fma2(acc[r][cp], tt[k][r], w[cp]);
            }
        }
    }

#pragma unroll
    for (int r = 0; r < 4; r++) {
        if (!valid[r]) continue;
#pragma unroll
        for (int j = 0; j < 4; j++) {
            float4 o = out4[(rows[r] << 4) + cg * 4 + j];
            float2 lo = unpack2(acc[r][2 * j]);
            float2 hi = unpack2(acc[r][2 * j + 1]);
            o.x += lo.x; o.y += lo.y; o.z += hi.x; o.w += hi.y;
            out4[(rows[r] << 4) + cg * 4 + j] = o;
        }
    }
}

// ---------------------------------------------------------------------------
// launch (graph-capturable; capture-safe fork/join to overlap gemm0 with fill)
// ---------------------------------------------------------------------------
extern "C" void kernel_launch(void* const* d_in, const int* in_sizes, int n_in,
                              void* d_out, int out_size) {
    const float* feat = (const float*)d_in[0];
    const float* W    = (const float*)d_in[1];
    const float* bias = (const float*)d_in[2];
    const int*   esrc = (const int*)d_in[3];
    const int*   edst = (const int*)d_in[4];
    float*       out  = (float*)d_out;

    void *p_degi = nullptr, *p_tot = nullptr;
    cudaGetSymbolAddress(&p_degi, g_degi);
    cudaGetSymbolAddress(&p_tot,  g_tot);
    cudaMemsetAsync(p_degi, 0, NN * sizeof(int));
    cudaMemsetAsync(p_tot,  0, 128 * sizeof(int));

    // Lazily-created side stream + events (host objects; no device memory).
    static cudaStream_t s_side = nullptr;
    static cudaEvent_t  s_fork = nullptr, s_join = nullptr;
    static bool s_tried = false;
    if (!s_tried) {
        s_tried = true;
        if (cudaStreamCreateWithFlags(&s_side, cudaStreamNonBlocking) != cudaSuccess)
            s_side = nullptr;
        if (s_side) {
            if (cudaEventCreateWithFlags(&s_fork, cudaEventDisableTiming) != cudaSuccess ||
                cudaEventCreateWithFlags(&s_join, cudaEventDisableTiming) != cudaSuccess) {
                s_side = nullptr;
            }
        }
    }
    const bool use_side = (s_side != nullptr);

    const int T = 256;
    const int GEMM_GRID = (NN + 255) / 256;

    deg_kernel<<<(NE / 4 + T - 1) / T, T>>>((const int4*)edst);
    scan_kernel<<<NB, 1024>>>();

    if (use_side) {
        cudaEventRecord(s_fork, 0);
        cudaStreamWaitEvent(s_side, s_fork, 0);
        gemm0_xs16_kernel<<<GEMM_GRID, 256, 0, s_side>>>(
            (const float4*)feat, (const float4*)W, (const float4*)bias,
            (float4*)out);
        cudaEventRecord(s_join, s_side);
        fill_kernel<<<(NE / 4 + T - 1) / T, T>>>((const int4*)esrc,
                                                 (const int4*)edst);
        cudaStreamWaitEvent(0, s_join, 0);
    } else {
        fill_kernel<<<(NE / 4 + T - 1) / T, T>>>((const int4*)esrc,
                                                 (const int4*)edst);
        gemm0_xs16_kernel<<<GEMM_GRID, 256>>>(
            (const float4*)feat, (const float4*)W, (const float4*)bias,
            (float4*)out);
    }

    gather_kernel<0><<<(NN * 8 + T - 1) / T, T>>>();
    gather_kernel<1><<<(NN * 8 + T - 1) / T, T>>>();

    final2_kernel<<<GEMM_GRID, 256>>>((const float4*)W, (float4*)out);
}

// round 12
// speedup vs baseline: 1.0550x; 1.0550x over previous
#include <cuda_runtime.h>
#include <cuda_fp16.h>

// Problem constants (fixed by the reference).
#define NN 100000
#define DD 64
#define NROW4 16             // float4s per 64-float fp32 row
#define NE 1600000
#define NB 98                // ceil(NN / 1024) scan blocks
#define NE_PAD (NE + 4 * NN) // padded adjacency capacity (gaps never read)
#define READYBIT 0x40000000

// Chebyshev coefficients for lambda_max = 2.0 (constant-fold: C1A=-1, C1B=0,
// C2A=-2, C2B=0).
#define C1A (-2.0f / 2.0f)
#define C1B (2.0f / 2.0f - 1.0f)
#define C2A (-4.0f / 2.0f)
#define C2B (4.0f / 2.0f - 2.0f)

typedef unsigned long long ull;

// Scratch (device globals: no allocation allowed in kernel_launch).
__device__ int    g_degi  [NN];
__device__ int    g_tot   [128];        // per-block padded totals | READYBIT
__device__ int    g_rowptr[NN];         // aligned segment starts (mult. of 4)
__device__ int    g_cursor[NN];
__device__ __align__(16) int g_adj[NE_PAD];
__device__ float  g_norm  [NN];
__device__ float  g_norm2 [NN];
__device__ uint4  g_xs16  [NN * 8];     // fp16 rows: norm[s]*feat[s]
__device__ uint4  g_y16   [NN * 8];     // fp16 rows: norm2[s]*h0[s]
__device__ float4 g_h0    [NN * NROW4]; // fp32 aggregation sums, pass 1
__device__ float4 g_h1    [NN * NROW4]; // fp32 aggregation sums, pass 2 (xC1A)

// ---------------------------------------------------------------------------
// bit-cast helpers (no HW cost)
// ---------------------------------------------------------------------------
__device__ __forceinline__ float2 u32_to_f2(unsigned u) {
    __half2 h = *reinterpret_cast<__half2*>(&u);
    return __half22float2(h);
}
__device__ __forceinline__ unsigned h2_to_u32(__half2 h) {
    return *reinterpret_cast<unsigned*>(&h);
}

// ---------------------------------------------------------------------------
// f32x2 packed-FMA helpers (Blackwell)
// ---------------------------------------------------------------------------
__device__ __forceinline__ ull pack2(float v) {
    ull r;
    asm("mov.b64 %0, {%1, %1};" : "=l"(r) : "f"(v));
    return r;
}
__device__ __forceinline__ void fma2(ull& d, ull a, ull b) {
    asm("fma.rn.f32x2 %0, %1, %2, %0;" : "+l"(d) : "l"(a), "l"(b));
}
__device__ __forceinline__ float2 unpack2(ull v) {
    float2 r;
    asm("mov.b64 {%0, %1}, %2;" : "=f"(r.x), "=f"(r.y) : "l"(v));
    return r;
}

// ---------------------------------------------------------------------------
// 1) degree histogram (int): deg[dst] += 1
// ---------------------------------------------------------------------------
__global__ void deg_kernel(const int4* __restrict__ dst4) {
    int t = blockIdx.x * blockDim.x + threadIdx.x;
    if (t < NE / 4) {
        int4 d = __ldg(dst4 + t);
        atomicAdd(&g_degi[d.x], 1);
        atomicAdd(&g_degi[d.y], 1);
        atomicAdd(&g_degi[d.z], 1);
        atomicAdd(&g_degi[d.w], 1);
    }
}

// ---------------------------------------------------------------------------
// 2) single-kernel scan (decoupled lookback, 98 co-resident blocks):
//    exclusive scan of PADDED degrees -> aligned starts; also norm / norm2.
// ---------------------------------------------------------------------------
__global__ __launch_bounds__(1024) void scan_kernel() {
    __shared__ int wsum[32];
    __shared__ int pre[128];
    __shared__ int s_off;
    int tid = threadIdx.x, lane = tid & 31, wid = tid >> 5;
    int b = blockIdx.x;
    int i = b * 1024 + tid;
    int deg = (i < NN) ? g_degi[i] : 0;
    int v = (deg + 3) & ~3;          // padded degree (aligned segment size)
    int x = v;
#pragma unroll
    for (int off = 1; off < 32; off <<= 1) {
        int y = __shfl_up_sync(~0u, x, off);
        if (lane >= off) x += y;
    }
    if (lane == 31) wsum[wid] = x;
    __syncthreads();
    if (wid == 0) {
        int w = wsum[lane];
#pragma unroll
        for (int off = 1; off < 32; off <<= 1) {
            int y = __shfl_up_sync(~0u, w, off);
            if (lane >= off) w += y;
        }
        wsum[lane] = w;
    }
    __syncthreads();
    int warpoff = (wid > 0) ? wsum[wid - 1] : 0;
    int btotal  = wsum[31];

    if (tid == 0) atomicExch(&g_tot[b], btotal | READYBIT);

    if (tid < b) {
        int p;
        do { p = atomicAdd(&g_tot[tid], 0); } while (!(p & READYBIT));
        pre[tid] = p & ~READYBIT;
    } else if (tid < 128) {
        pre[tid] = 0;
    }
    __syncthreads();
    if (wid == 0) {
        int s = pre[lane] + pre[lane + 32] + pre[lane + 64] + pre[lane + 96];
#pragma unroll
        for (int off = 16; off > 0; off >>= 1)
            s += __shfl_down_sync(~0u, s, off);
        if (lane == 0) s_off = s;
    }
    __syncthreads();

    if (i < NN) {
        int ex = s_off + warpoff + x - v;   // exclusive padded prefix
        g_rowptr[i] = ex;
        g_cursor[i] = ex;
        float nv = rsqrtf(fmaxf((float)deg, 1.0f));
        g_norm[i]  = nv;
        g_norm2[i] = nv * nv;
    }
}

// ---------------------------------------------------------------------------
// 3) CSR fill: adj[cursor[dst]++] = src  (exact lengths; gaps never read)
// ---------------------------------------------------------------------------
__global__ void fill_kernel(const int4* __restrict__ src4,
                            const int4* __restrict__ dst4) {
    int t = blockIdx.x * blockDim.x + threadIdx.x;
    if (t < NE / 4) {
        int4 s = __ldg(src4 + t);
        int4 d = __ldg(dst4 + t);
        g_adj[atomicAdd(&g_cursor[d.x], 1)] = s.x;
        g_adj[atomicAdd(&g_cursor[d.y], 1)] = s.y;
        g_adj[atomicAdd(&g_cursor[d.z], 1)] = s.z;
        g_adj[atomicAdd(&g_cursor[d.w], 1)] = s.w;
    }
}

// ---------------------------------------------------------------------------
// 4) scale16: xs16[i] = half(norm[i] * feat[i])   (8 threads per row)
//    Runs on the side stream, overlapped with fill (both depend on scan only).
// ---------------------------------------------------------------------------
__global__ void scale16_kernel(const float4* __restrict__ feat4) {
    int t = blockIdx.x * blockDim.x + threadIdx.x;   // grid covers NN*8 exactly
    int i = t >> 3;
    int c = t & 7;
    float nv = g_norm[i];
    float4 f0 = __ldg(feat4 + (i << 4) + c * 2);
    float4 f1 = __ldg(feat4 + (i << 4) + c * 2 + 1);
    uint4 u;
    u.x = h2_to_u32(__floats2half2_rn(nv * f0.x, nv * f0.y));
    u.y = h2_to_u32(__floats2half2_rn(nv * f0.z, nv * f0.w));
    u.z = h2_to_u32(__floats2half2_rn(nv * f1.x, nv * f1.y));
    u.w = h2_to_u32(__floats2half2_rn(nv * f1.z, nv * f1.w));
    g_xs16[t] = u;
}

// ---------------------------------------------------------------------------
// 5) gather passes. 8 threads per node; each thread owns 8 halves (16B).
//    One LDG.128 per edge per thread; fp32 accumulation; no scalar loads.
//    PASS 0: h0[i] = sum xs16[s]; epilogue writes h0 (fp32) and
//            y16[i] = half(norm2[i]*h0[i]).
//    PASS 1: h1[i] = C1A * sum y16[s]  (fp32).
// ---------------------------------------------------------------------------
template <int PASS>
__global__ __launch_bounds__(256) void gather_kernel() {
    int t = blockIdx.x * blockDim.x + threadIdx.x;   // grid covers NN*8 exactly
    int i = t >> 3;
    int c = t & 7;

    int j   = g_rowptr[i];       // multiple of 4
    int end = j + g_degi[i];
    const uint4* __restrict__ src = (PASS == 0) ? g_xs16 : g_y16;

    float a0 = 0.f, a1 = 0.f, a2 = 0.f, a3 = 0.f;
    float a4 = 0.f, a5 = 0.f, a6 = 0.f, a7 = 0.f;
    float b0 = 0.f, b1 = 0.f, b2 = 0.f, b3 = 0.f;
    float b4 = 0.f, b5 = 0.f, b6 = 0.f, b7 = 0.f;

#define EDGE_ACC(P0,P1,P2,P3,P4,P5,P6,P7, S)                                 \
    {                                                                        \
        uint4 u = __ldg(src + ((S) << 3) + c);                               \
        float2 f0 = u32_to_f2(u.x);                                          \
        float2 f1 = u32_to_f2(u.y);                                          \
        float2 f2 = u32_to_f2(u.z);                                          \
        float2 f3 = u32_to_f2(u.w);                                          \
        P0 += f0.x; P1 += f0.y; P2 += f1.x; P3 += f1.y;                      \
        P4 += f2.x; P5 += f2.y; P6 += f3.x; P7 += f3.y;                      \
    }
#define EDGE_A(S) EDGE_ACC(a0,a1,a2,a3,a4,a5,a6,a7, S)
#define EDGE_B(S) EDGE_ACC(b0,b1,b2,b3,b4,b5,b6,b7, S)

    for (; j + 8 <= end; j += 8) {
        int4 p0 = *reinterpret_cast<const int4*>(&g_adj[j]);
        int4 p1 = *reinterpret_cast<const int4*>(&g_adj[j + 4]);
        EDGE_A(p0.x); EDGE_B(p0.y); EDGE_A(p0.z); EDGE_B(p0.w);
        EDGE_A(p1.x); EDGE_B(p1.y); EDGE_A(p1.z); EDGE_B(p1.w);
    }
    if (j + 4 <= end) {
        int4 p0 = *reinterpret_cast<const int4*>(&g_adj[j]);
        EDGE_A(p0.x); EDGE_B(p0.y); EDGE_A(p0.z); EDGE_B(p0.w);
        j += 4;
    }
    for (; j < end; j++) {
        EDGE_A(g_adj[j]);
    }
#undef EDGE_A
#undef EDGE_B
#undef EDGE_ACC

    float r0 = a0 + b0, r1 = a1 + b1, r2 = a2 + b2, r3 = a3 + b3;
    float r4 = a4 + b4, r5 = a5 + b5, r6 = a6 + b6, r7 = a7 + b7;

    if (PASS == 0) {
        g_h0[(i << 4) + c * 2]     = make_float4(r0, r1, r2, r3);
        g_h0[(i << 4) + c * 2 + 1] = make_float4(r4, r5, r6, r7);
        float n2 = g_norm2[i];
        uint4 u;
        u.x = h2_to_u32(__floats2half2_rn(n2 * r0, n2 * r1));
        u.y = h2_to_u32(__floats2half2_rn(n2 * r2, n2 * r3));
        u.z = h2_to_u32(__floats2half2_rn(n2 * r4, n2 * r5));
        u.w = h2_to_u32(__floats2half2_rn(n2 * r6, n2 * r7));
        g_y16[t] = u;
    } else {
        g_h1[(i << 4) + c * 2] =
            make_float4(C1A * r0, C1A * r1, C1A * r2, C1A * r3);
        g_h1[(i << 4) + c * 2 + 1] =
            make_float4(C1A * r4, C1A * r5, C1A * r6, C1A * r7);
    }
}

// ---------------------------------------------------------------------------
// 6) fused epilogue GEMM (proven R9 version):
//    t0 = feat;  t1 = c1a*n*h0;  t2 = c2a*n*h1 + c2b*t1 - t0
//    out = t0@W0 + t1@W1 + t2@W2 + bias
// ---------------------------------------------------------------------------
__global__ __launch_bounds__(256) void final_kernel(
    const float4* __restrict__ feat4,
    const float4* __restrict__ W4,
    const float4* __restrict__ bias4,
    float4* __restrict__ out4) {
    __shared__ __align__(16) float Ws[3 * 64 * 64];   // 49152 B
    {
        float4* Ws4 = reinterpret_cast<float4*>(Ws);
        for (int i = threadIdx.x; i < 3 * 64 * 16; i += 256)
            Ws4[i] = __ldg(W4 + i);
    }
    __syncthreads();

    const int cg   = threadIdx.x >> 6;
    const int rg   = threadIdx.x & 63;
    const int base = blockIdx.x * 256;

    int   rows[4];
    bool  valid[4];
    float n[4];
#pragma unroll
    for (int r = 0; r < 4; r++) {
        int row  = base + rg + 64 * r;
        valid[r] = row < NN;
        rows[r]  = valid[r] ? row : 0;
        n[r]     = g_norm[rows[r]];
    }

    ull acc[4][8];
#pragma unroll
    for (int r = 0; r < 4; r++)
#pragma unroll
        for (int cp = 0; cp < 8; cp++) acc[r][cp] = 0ULL;

    const ulonglong2* Wp = reinterpret_cast<const ulonglong2*>(Ws);

    for (int dc = 0; dc < 16; dc++) {
        float4 a0[4], a1[4], a2[4];
#pragma unroll
        for (int r = 0; r < 4; r++) {
            int b = (rows[r] << 4) + dc;
            a0[r] = __ldg(feat4 + b);
            a1[r] = g_h0[b];
            a2[r] = g_h1[b];
        }
#pragma unroll
        for (int s = 0; s < 4; s++) {
            const int d = dc * 4 + s;
            ull tt[3][4];
#pragma unroll
            for (int r = 0; r < 4; r++) {
                float t0  = reinterpret_cast<const float*>(&a0[r])[s];
                float h0v = reinterpret_cast<const float*>(&a1[r])[s];
                float h1v = reinterpret_cast<const float*>(&a2[r])[s];
                float t1 = fmaf(C1A * n[r], h0v, C1B * t0);
                float t2 = fmaf(C2A * n[r], h1v, fmaf(C2B, t1, -t0));
                tt[0][r] = pack2(t0);
                tt[1][r] = pack2(t1);
                tt[2][r] = pack2(t2);
            }
#pragma unroll
            for (int k = 0; k < 3; k++) {
                const ulonglong2* p = Wp + (k * 1024 + d * 16 + cg * 4);
                ull w[8];
#pragma unroll
                for (int j = 0; j < 4; j++) {
                    ulonglong2 v = p[j];       // LDS.128, warp-uniform broadcast
                    w[2 * j]     = v.x;
                    w[2 * j + 1] = v.y;
                }
#pragma unroll
                for (int r = 0; r < 4; r++)
#pragma unroll
                    for (int cp = 0; cp < 8; cp++)
                        fma2(acc[r][cp], tt[k][r], w[cp]);
            }
        }
    }

    float4 b4[4];
#pragma unroll
    for (int j = 0; j < 4; j++) b4[j] = __ldg(bias4 + cg * 4 + j);
#pragma unroll
    for (int r = 0; r < 4; r++) {
        if (!valid[r]) continue;
#pragma unroll
        for (int j = 0; j < 4; j++) {
            float2 lo = unpack2(acc[r][2 * j]);
            float2 hi = unpack2(acc[r][2 * j + 1]);
            float4 o;
            o.x = lo.x + b4[j].x;
            o.y = lo.y + b4[j].y;
            o.z = hi.x + b4[j].z;
            o.w = hi.y + b4[j].w;
            out4[(rows[r] << 4) + cg * 4 + j] = o;
        }
    }
}

// ---------------------------------------------------------------------------
// launch (graph-capturable; fork/join overlaps scale16 with fill)
// ---------------------------------------------------------------------------
extern "C" void kernel_launch(void* const* d_in, const int* in_sizes, int n_in,
                              void* d_out, int out_size) {
    const float* feat = (const float*)d_in[0];
    const float* W    = (const float*)d_in[1];
    const float* bias = (const float*)d_in[2];
    const int*   esrc = (const int*)d_in[3];
    const int*   edst = (const int*)d_in[4];
    float*       out  = (float*)d_out;

    void *p_degi = nullptr, *p_tot = nullptr;
    cudaGetSymbolAddress(&p_degi, g_degi);
    cudaGetSymbolAddress(&p_tot,  g_tot);
    cudaMemsetAsync(p_degi, 0, NN * sizeof(int));
    cudaMemsetAsync(p_tot,  0, 128 * sizeof(int));

    // Lazily-created side stream + events (host objects; no device memory).
    static cudaStream_t s_side = nullptr;
    static cudaEvent_t  s_fork = nullptr, s_join = nullptr;
    static bool s_tried = false;
    if (!s_tried) {
        s_tried = true;
        if (cudaStreamCreateWithFlags(&s_side, cudaStreamNonBlocking) != cudaSuccess)
            s_side = nullptr;
        if (s_side) {
            if (cudaEventCreateWithFlags(&s_fork, cudaEventDisableTiming) != cudaSuccess ||
                cudaEventCreateWithFlags(&s_join, cudaEventDisableTiming) != cudaSuccess) {
                s_side = nullptr;
            }
        }
    }
    const bool use_side = (s_side != nullptr);

    const int T = 256;

    deg_kernel<<<(NE / 4 + T - 1) / T, T>>>((const int4*)edst);
    scan_kernel<<<NB, 1024>>>();

    if (use_side) {
        cudaEventRecord(s_fork, 0);
        cudaStreamWaitEvent(s_side, s_fork, 0);
        scale16_kernel<<<NN * 8 / T, T, 0, s_side>>>((const float4*)feat);
        cudaEventRecord(s_join, s_side);
        fill_kernel<<<(NE / 4 + T - 1) / T, T>>>((const int4*)esrc,
                                                 (const int4*)edst);
        cudaStreamWaitEvent(0, s_join, 0);
    } else {
        fill_kernel<<<(NE / 4 + T - 1) / T, T>>>((const int4*)esrc,
                                                 (const int4*)edst);
        scale16_kernel<<<NN * 8 / T, T>>>((const float4*)feat);
    }

    gather_kernel<0><<<NN * 8 / T, T>>>();
    gather_kernel<1><<<NN * 8 / T, T>>>();

    final_kernel<<<(NN + 255) / 256, 256>>>((const float4*)feat,
                                            (const float4*)W,
                                            (const float4*)bias,
                                            (float4*)out);
}